// round 11
// baseline (speedup 1.0000x reference)
#include <cuda_runtime.h>
#include <cuda_bf16.h>
#include <cstdint>

#define B    64
#define HID  768
#define VSZ  30000
#define TLEN 32
#define C1   512

// logits HMMA tiling (MT=64, double-buffered dynamic smem)
#define MT      64
#define KC      64
#define NCHUNK  (HID / KC)              // 12
#define GRID_L  ((VSZ + MT - 1) / MT)   // 469
#define LSTG    32768                   // per-stage bytes: Whi 8K|Wlo 8K|Hhi 8K|Hlo 8K

// gates HMMA tiling (round-7 proven)
#define KSG     4                       // split-K
#define CHG     6                       // chunks of 64 per split (384 k)

__device__ float g_c[B * HID];          // transposed: [u][b]
__device__ float g_hidden[B * C1];
__device__ unsigned long long g_amax[2][B];
__device__ float g_gpartT[KSG][4 * HID][B];
__device__ __nv_bfloat16 g_Whi[(size_t)VSZ * HID];
__device__ __nv_bfloat16 g_Wlo[(size_t)VSZ * HID];
__device__ __nv_bfloat16 g_Ehi[(size_t)VSZ * HID];
__device__ __nv_bfloat16 g_Elo[(size_t)VSZ * HID];
__device__ __nv_bfloat16 g_WihHi[4 * HID * HID];
__device__ __nv_bfloat16 g_WihLo[4 * HID * HID];
__device__ __nv_bfloat16 g_WhhHi[4 * HID * HID];
__device__ __nv_bfloat16 g_WhhLo[4 * HID * HID];
__device__ __nv_bfloat16 g_hhi[B * HID];
__device__ __nv_bfloat16 g_hlo[B * HID];

__device__ __forceinline__ unsigned int ford(float f) {
    unsigned int u = __float_as_uint(f);
    return u ^ (((int)u >> 31) | 0x80000000u);
}
__device__ __forceinline__ float sigm(float x) { return 1.0f / (1.0f + expf(-x)); }

__device__ __forceinline__ uint32_t smem_u32(const void* p) {
    uint32_t a;
    asm("{ .reg .u64 t; cvta.to.shared.u64 t, %1; cvt.u32.u64 %0, t; }" : "=r"(a) : "l"(p));
    return a;
}

#define LDSM4(r0, r1, r2, r3, addr) \
    asm volatile("ldmatrix.sync.aligned.m8n8.x4.shared.b16 {%0,%1,%2,%3}, [%4];" \
                 : "=r"(r0), "=r"(r1), "=r"(r2), "=r"(r3) : "r"(addr))

#define MMA16816(d, a, bf) \
    asm volatile("mma.sync.aligned.m16n8k16.row.col.f32.bf16.bf16.f32 " \
                 "{%0,%1,%2,%3}, {%4,%5,%6,%7}, {%8,%9}, {%0,%1,%2,%3};" \
                 : "+f"((d)[0]), "+f"((d)[1]), "+f"((d)[2]), "+f"((d)[3]) \
                 : "r"((a)[0]), "r"((a)[1]), "r"((a)[2]), "r"((a)[3]), \
                   "r"((bf)[0]), "r"((bf)[1]))

// ---------------------------------------------------------------------------
__global__ void init_kernel(const float* __restrict__ fused) {
    int i = blockIdx.x * blockDim.x + threadIdx.x;
    if (i < B * HID) {
        float v = fused[i];
        __nv_bfloat16 hi = __float2bfloat16(v);
        g_hhi[i] = hi;
        g_hlo[i] = __float2bfloat16(v - __bfloat162float(hi));
        g_c[i] = 0.0f;
    }
    if (blockIdx.x == 0 && threadIdx.x < B) {
        g_amax[0][threadIdx.x] = 0ull;
        g_amax[1][threadIdx.x] = 0ull;
    }
}

// ---------------------------------------------------------------------------
__global__ void split_kernel(const float* __restrict__ src,
                             __nv_bfloat16* __restrict__ hi,
                             __nv_bfloat16* __restrict__ lo, size_t n) {
    size_t stride = (size_t)gridDim.x * blockDim.x * 4;
    for (size_t i = ((size_t)blockIdx.x * blockDim.x + threadIdx.x) * 4; i < n; i += stride) {
        float4 x = *(const float4*)(src + i);
        __nv_bfloat16 h0 = __float2bfloat16(x.x);
        __nv_bfloat16 h1 = __float2bfloat16(x.y);
        __nv_bfloat16 h2 = __float2bfloat16(x.z);
        __nv_bfloat16 h3 = __float2bfloat16(x.w);
        hi[i] = h0; hi[i + 1] = h1; hi[i + 2] = h2; hi[i + 3] = h3;
        lo[i]     = __float2bfloat16(x.x - __bfloat162float(h0));
        lo[i + 1] = __float2bfloat16(x.y - __bfloat162float(h1));
        lo[i + 2] = __float2bfloat16(x.z - __bfloat162float(h2));
        lo[i + 3] = __float2bfloat16(x.w - __bfloat162float(h3));
    }
}

// ---------------------------------------------------------------------------
__global__ void closed1_kernel(const float* __restrict__ fused,
                               const float* __restrict__ c1_W,
                               const float* __restrict__ c1_b) {
    __shared__ float w[HID];
    int j = blockIdx.x;
    for (int k = threadIdx.x; k < HID; k += 64) w[k] = c1_W[j * HID + k];
    __syncthreads();
    int b = threadIdx.x;
    float acc = 0.0f;
    for (int k = 0; k < HID; ++k) acc += fused[b * HID + k] * w[k];
    acc += c1_b[j];
    g_hidden[b * C1 + j] = fmaxf(acc, 0.0f);
}

__global__ void closed2_kernel(const float* __restrict__ c2_W,
                               const float* __restrict__ c2_b,
                               float* __restrict__ out) {
    int wid = threadIdx.x >> 5, lane = threadIdx.x & 31;
    int o = blockIdx.x * 4 + wid;
    int b = o >> 1, cls = o & 1;
    float acc = 0.0f;
    for (int k = lane; k < C1; k += 32)
        acc += g_hidden[b * C1 + k] * c2_W[cls * C1 + k];
#pragma unroll
    for (int off = 16; off; off >>= 1)
        acc += __shfl_xor_sync(0xFFFFFFFFu, acc, off);
    if (lane == 0) out[b * 2 + cls] = acc + c2_b[cls];
}

// ---------------------------------------------------------------------------
// gates via HMMA split-bf16 (exact round-7/10 structure — proven)
// ---------------------------------------------------------------------------
__global__ void __launch_bounds__(256, 2)
gates_mma(int t, float* __restrict__ out) {
    __shared__ __align__(128) __nv_bfloat16 sAhi[64 * KC];
    __shared__ __align__(128) __nv_bfloat16 sAlo[64 * KC];
    __shared__ __align__(128) __nv_bfloat16 sBhi[B * KC];
    __shared__ __align__(128) __nv_bfloat16 sBlo[B * KC];
    __shared__ int tok_s[B];

    const int tid = threadIdx.x, wid = tid >> 5, lane = tid & 31;
    const int mw = wid >> 1, nw = wid & 1;
    const int mtile = blockIdx.x;
    const int ks = blockIdx.y;
    const bool is_x = ks < 2;
    const int kbase = (ks & 1) * 384;

    if (tid < B) {
        int tok = 0;
        if (t > 0) tok = (int)(~(unsigned int)(g_amax[(t - 1) & 1][tid]));
        tok_s[tid] = tok;
        if (mtile == 0 && ks == 0) {
            g_amax[t & 1][tid] = 0ull;
            if (t > 0) out[2 * B + tid * TLEN + (t - 1)] = (float)tok;
        }
    }
    __syncthreads();

    const __nv_bfloat16* srcp[8];
    uint32_t dsta[8];
#pragma unroll
    for (int i = 0; i < 8; ++i) {
        int s = tid + i * 256;
        int r = (s & 511) >> 3, g = s & 7;
        uint32_t dst = (uint32_t)(r * 128 + ((g ^ (r & 7)) * 16));
        if (s < 512) {
            int m = mtile * 64 + r;
            srcp[i] = (is_x ? g_WihHi : g_WhhHi) + (size_t)m * HID + kbase + g * 8;
            dsta[i] = smem_u32(sAhi) + dst;
        } else if (s < 1024) {
            int m = mtile * 64 + r;
            srcp[i] = (is_x ? g_WihLo : g_WhhLo) + (size_t)m * HID + kbase + g * 8;
            dsta[i] = smem_u32(sAlo) + dst;
        } else if (s < 1536) {
            srcp[i] = is_x ? (g_Ehi + (size_t)tok_s[r] * HID + kbase + g * 8)
                           : (g_hhi + r * HID + kbase + g * 8);
            dsta[i] = smem_u32(sBhi) + dst;
        } else {
            srcp[i] = is_x ? (g_Elo + (size_t)tok_s[r] * HID + kbase + g * 8)
                           : (g_hlo + r * HID + kbase + g * 8);
            dsta[i] = smem_u32(sBlo) + dst;
        }
    }

    const int mA = mw * 16 + ((lane >> 3) & 1) * 8 + (lane & 7);
    const int gAo = lane >> 4;
    const int nB = nw * 32 + ((lane >> 4) & 1) * 8 + (lane & 7);
    const int gBo = (lane >> 3) & 1;
    const uint32_t sAhiB = smem_u32(sAhi), sAloB = smem_u32(sAlo);
    const uint32_t sBhiB = smem_u32(sBhi), sBloB = smem_u32(sBlo);

    float acc[4][4];
#pragma unroll
    for (int n = 0; n < 4; ++n)
#pragma unroll
        for (int j = 0; j < 4; ++j) acc[n][j] = 0.0f;

    uint4 pf[8];
#pragma unroll
    for (int i = 0; i < 8; ++i) { pf[i] = *(const uint4*)srcp[i]; srcp[i] += KC; }

    for (int c = 0; c < CHG; ++c) {
#pragma unroll
        for (int i = 0; i < 8; ++i)
            asm volatile("st.shared.v4.b32 [%0], {%1, %2, %3, %4};"
                         :: "r"(dsta[i]), "r"(pf[i].x), "r"(pf[i].y),
                            "r"(pf[i].z), "r"(pf[i].w) : "memory");
        __syncthreads();

        if (c + 1 < CHG) {
#pragma unroll
            for (int i = 0; i < 8; ++i) { pf[i] = *(const uint4*)srcp[i]; srcp[i] += KC; }
        }

#pragma unroll
        for (int step = 0; step < 4; ++step) {
            const int g0 = step * 2;
            const int gA = g0 + gAo;
            const uint32_t offA = (uint32_t)(mA * 128 + ((gA ^ (mA & 7)) * 16));
            uint32_t ahi[4], alo[4];
            LDSM4(ahi[0], ahi[1], ahi[2], ahi[3], sAhiB + offA);
            LDSM4(alo[0], alo[1], alo[2], alo[3], sAloB + offA);

            uint32_t bhi[4][2], blo[4][2];
#pragma unroll
            for (int ntp = 0; ntp < 2; ++ntp) {
                const int nr = nB + ntp * 16;
                const int gB = g0 + gBo;
                const uint32_t offB = (uint32_t)(nr * 128 + ((gB ^ (nr & 7)) * 16));
                LDSM4(bhi[ntp * 2][0], bhi[ntp * 2][1],
                      bhi[ntp * 2 + 1][0], bhi[ntp * 2 + 1][1], sBhiB + offB);
                LDSM4(blo[ntp * 2][0], blo[ntp * 2][1],
                      blo[ntp * 2 + 1][0], blo[ntp * 2 + 1][1], sBloB + offB);
            }
#pragma unroll
            for (int n = 0; n < 4; ++n) {
                MMA16816(acc[n], ahi, bhi[n]);
                MMA16816(acc[n], ahi, blo[n]);
                MMA16816(acc[n], alo, bhi[n]);
            }
        }
        __syncthreads();
    }

    const int laneg = lane >> 2, lane4 = lane & 3;
    const int row_lo = mtile * 64 + mw * 16 + laneg;
    const int row_hi = row_lo + 8;
#pragma unroll
    for (int n = 0; n < 4; ++n) {
        int col = nw * 32 + n * 8 + lane4 * 2;
        *(float2*)&g_gpartT[ks][row_lo][col] = make_float2(acc[n][0], acc[n][1]);
        *(float2*)&g_gpartT[ks][row_hi][col] = make_float2(acc[n][2], acc[n][3]);
    }
}

// ---------------------------------------------------------------------------
// cell: reduce KSG partials (fixed order), biases, LSTM nonlinearities,
// emit bf16 hi/lo split of h. (exact round-7/10)
// ---------------------------------------------------------------------------
__global__ void cell_kernel(const float* __restrict__ b_ih,
                            const float* __restrict__ b_hh, int t) {
    int idx = blockIdx.x * blockDim.x + threadIdx.x;
    if (idx >= B * HID) return;
    int b = idx & (B - 1), u = idx >> 6;

    float gi = b_ih[u] + b_hh[u];
    float gf = b_ih[HID + u] + b_hh[HID + u];
    float gg = b_ih[2 * HID + u] + b_hh[2 * HID + u];
    float go = b_ih[3 * HID + u] + b_hh[3 * HID + u];
#pragma unroll
    for (int s = 0; s < KSG; ++s) {
        gi += g_gpartT[s][u][b];
        gf += g_gpartT[s][HID + u][b];
        gg += g_gpartT[s][2 * HID + u][b];
        go += g_gpartT[s][3 * HID + u][b];
    }
    float cn = sigm(gf) * g_c[u * B + b] + sigm(gi) * tanhf(gg);
    g_c[u * B + b] = cn;
    float hn = sigm(go) * tanhf(cn);
    __nv_bfloat16 hi = __float2bfloat16(hn);
    g_hhi[b * HID + u] = hi;
    g_hlo[b * HID + u] = __float2bfloat16(hn - __bfloat162float(hi));
}

// ---------------------------------------------------------------------------
// logits via HMMA split-bf16 — round-6 structure with DOUBLE-BUFFERED smem:
// one __syncthreads per chunk; STS(c+1) to the opposite stage is issued
// before compute(c), overlapping store and MMA. Dynamic smem = 2 x 32KB.
// ---------------------------------------------------------------------------
__global__ void __launch_bounds__(256, 2)
logits_mma(const float* __restrict__ out_b, int t) {
    extern __shared__ __align__(128) char dsm[];
    __shared__ unsigned long long skeys[4][B];

    const int tid = threadIdx.x, wid = tid >> 5, lane = tid & 31;
    const int mw = wid >> 1, nw = wid & 1;
    const int v0 = blockIdx.x * MT;
    const uint32_t sb0 = smem_u32(dsm);

    const __nv_bfloat16* srcp[8];
    uint32_t dstrel[8];
#pragma unroll
    for (int i = 0; i < 8; ++i) {
        int s = tid + i * 256;
        int r = (s & 511) >> 3, g = s & 7;
        uint32_t dst = (uint32_t)(r * 128 + ((g ^ (r & 7)) * 16));
        if (s < 512) {
            int v = v0 + r; if (v >= VSZ) v = VSZ - 1;
            srcp[i] = g_Whi + (size_t)v * HID + g * 8;
            dstrel[i] = dst;                  // Whi @ 0
        } else if (s < 1024) {
            int v = v0 + r; if (v >= VSZ) v = VSZ - 1;
            srcp[i] = g_Wlo + (size_t)v * HID + g * 8;
            dstrel[i] = 8192 + dst;           // Wlo @ 8K
        } else if (s < 1536) {
            srcp[i] = g_hhi + r * HID + g * 8;
            dstrel[i] = 16384 + dst;          // Hhi @ 16K
        } else {
            srcp[i] = g_hlo + r * HID + g * 8;
            dstrel[i] = 24576 + dst;          // Hlo @ 24K
        }
    }

    const int mA = mw * 16 + ((lane >> 3) & 1) * 8 + (lane & 7);
    const int gAo = lane >> 4;
    const int nB = nw * 32 + ((lane >> 4) & 1) * 8 + (lane & 7);
    const int gBo = (lane >> 3) & 1;

    float acc[4][4];
#pragma unroll
    for (int n = 0; n < 4; ++n)
#pragma unroll
        for (int j = 0; j < 4; ++j) acc[n][j] = 0.0f;

    uint4 pf[8];
    // chunk 0 -> regs -> stage 0
#pragma unroll
    for (int i = 0; i < 8; ++i) { pf[i] = *(const uint4*)srcp[i]; srcp[i] += KC; }
#pragma unroll
    for (int i = 0; i < 8; ++i)
        asm volatile("st.shared.v4.b32 [%0], {%1, %2, %3, %4};"
                     :: "r"(sb0 + dstrel[i]), "r"(pf[i].x), "r"(pf[i].y),
                        "r"(pf[i].z), "r"(pf[i].w) : "memory");
    // prefetch chunk 1
#pragma unroll
    for (int i = 0; i < 8; ++i) { pf[i] = *(const uint4*)srcp[i]; srcp[i] += KC; }

    for (int c = 0; c < NCHUNK; ++c) {
        __syncthreads();   // stage[c&1] ready; stage[(c+1)&1] free (drained last iter)

        if (c + 1 < NCHUNK) {
            const uint32_t nb = sb0 + (uint32_t)((c + 1) & 1) * LSTG;
#pragma unroll
            for (int i = 0; i < 8; ++i)
                asm volatile("st.shared.v4.b32 [%0], {%1, %2, %3, %4};"
                             :: "r"(nb + dstrel[i]), "r"(pf[i].x), "r"(pf[i].y),
                                "r"(pf[i].z), "r"(pf[i].w) : "memory");
            if (c + 2 < NCHUNK) {
#pragma unroll
                for (int i = 0; i < 8; ++i) { pf[i] = *(const uint4*)srcp[i]; srcp[i] += KC; }
            }
        }

        const uint32_t sb = sb0 + (uint32_t)(c & 1) * LSTG;
        const uint32_t sWhiB = sb, sWloB = sb + 8192;
        const uint32_t sHhiB = sb + 16384, sHloB = sb + 24576;
#pragma unroll
        for (int step = 0; step < 4; ++step) {
            const int g0 = step * 2;
            const int gA = g0 + gAo;
            const uint32_t offA = (uint32_t)(mA * 128 + ((gA ^ (mA & 7)) * 16));
            uint32_t ahi[4], alo[4];
            LDSM4(ahi[0], ahi[1], ahi[2], ahi[3], sWhiB + offA);
            LDSM4(alo[0], alo[1], alo[2], alo[3], sWloB + offA);

            uint32_t bhi[4][2], blo[4][2];
#pragma unroll
            for (int ntp = 0; ntp < 2; ++ntp) {
                const int nr = nB + ntp * 16;
                const int gB = g0 + gBo;
                const uint32_t offB = (uint32_t)(nr * 128 + ((gB ^ (nr & 7)) * 16));
                LDSM4(bhi[ntp * 2][0], bhi[ntp * 2][1],
                      bhi[ntp * 2 + 1][0], bhi[ntp * 2 + 1][1], sHhiB + offB);
                LDSM4(blo[ntp * 2][0], blo[ntp * 2][1],
                      blo[ntp * 2 + 1][0], blo[ntp * 2 + 1][1], sHloB + offB);
            }
#pragma unroll
            for (int n = 0; n < 4; ++n) {
                MMA16816(acc[n], ahi, bhi[n]);
                MMA16816(acc[n], ahi, blo[n]);
                MMA16816(acc[n], alo, bhi[n]);
            }
        }
    }

    const int laneg = lane >> 2, lane4 = lane & 3;
    const int m_lo = v0 + mw * 16 + laneg;
    const int m_hi = m_lo + 8;
    const bool val_lo = m_lo < VSZ, val_hi = m_hi < VSZ;
    const float bias_lo = val_lo ? out_b[m_lo] : 0.0f;
    const float bias_hi = val_hi ? out_b[m_hi] : 0.0f;
    const unsigned int ni_lo = ~(unsigned int)m_lo, ni_hi = ~(unsigned int)m_hi;

#pragma unroll
    for (int n = 0; n < 4; ++n) {
        unsigned long long kA = 0ull, kB = 0ull;
        if (val_lo) {
            kA = ((unsigned long long)ford(acc[n][0] + bias_lo) << 32) | ni_lo;
            kB = ((unsigned long long)ford(acc[n][1] + bias_lo) << 32) | ni_lo;
        }
        if (val_hi) {
            unsigned long long k2 = ((unsigned long long)ford(acc[n][2] + bias_hi) << 32) | ni_hi;
            unsigned long long k3 = ((unsigned long long)ford(acc[n][3] + bias_hi) << 32) | ni_hi;
            if (k2 > kA) kA = k2;
            if (k3 > kB) kB = k3;
        }
#pragma unroll
        for (int off = 4; off < 32; off <<= 1) {
            unsigned long long oA = __shfl_xor_sync(0xFFFFFFFFu, kA, off);
            unsigned long long oB = __shfl_xor_sync(0xFFFFFFFFu, kB, off);
            if (oA > kA) kA = oA;
            if (oB > kB) kB = oB;
        }
        if (laneg == 0) {
            int ncol = nw * 32 + n * 8 + lane4 * 2;
            skeys[mw][ncol]     = kA;
            skeys[mw][ncol + 1] = kB;
        }
    }
    __syncthreads();
    if (tid < B) {
        unsigned long long k = skeys[0][tid];
        if (skeys[1][tid] > k) k = skeys[1][tid];
        if (skeys[2][tid] > k) k = skeys[2][tid];
        if (skeys[3][tid] > k) k = skeys[3][tid];
        atomicMax(&g_amax[t & 1][tid], k);
    }
}

// ---------------------------------------------------------------------------
__global__ void final_kernel(float* __restrict__ out) {
    int b = threadIdx.x;
    if (b < B) {
        int tok = (int)(~(unsigned int)(g_amax[(TLEN - 1) & 1][b]));
        out[2 * B + b * TLEN + (TLEN - 1)] = (float)tok;
    }
}

// ---------------------------------------------------------------------------
extern "C" void kernel_launch(void* const* d_in, const int* in_sizes, int n_in,
                              void* d_out, int out_size) {
    const float* fused = (const float*)d_in[0];
    const float* emb   = (const float*)d_in[1];
    const float* W_ih  = (const float*)d_in[2];
    const float* W_hh  = (const float*)d_in[3];
    const float* b_ih  = (const float*)d_in[4];
    const float* b_hh  = (const float*)d_in[5];
    const float* out_W = (const float*)d_in[6];
    const float* out_b = (const float*)d_in[7];
    const float* c1_W  = (const float*)d_in[8];
    const float* c1_b  = (const float*)d_in[9];
    const float* c2_W  = (const float*)d_in[10];
    const float* c2_b  = (const float*)d_in[11];
    float* out = (float*)d_out;

    cudaFuncSetAttribute(logits_mma, cudaFuncAttributeMaxDynamicSharedMemorySize,
                         2 * LSTG);

    __nv_bfloat16 *pWhi, *pWlo, *pEhi, *pElo, *pIhHi, *pIhLo, *pHhHi, *pHhLo;
    cudaGetSymbolAddress((void**)&pWhi, g_Whi);
    cudaGetSymbolAddress((void**)&pWlo, g_Wlo);
    cudaGetSymbolAddress((void**)&pEhi, g_Ehi);
    cudaGetSymbolAddress((void**)&pElo, g_Elo);
    cudaGetSymbolAddress((void**)&pIhHi, g_WihHi);
    cudaGetSymbolAddress((void**)&pIhLo, g_WihLo);
    cudaGetSymbolAddress((void**)&pHhHi, g_WhhHi);
    cudaGetSymbolAddress((void**)&pHhLo, g_WhhLo);

    init_kernel<<<(B * HID + 255) / 256, 256>>>(fused);
    split_kernel<<<2048, 256>>>(out_W, pWhi, pWlo, (size_t)VSZ * HID);
    split_kernel<<<2048, 256>>>(emb, pEhi, pElo, (size_t)VSZ * HID);
    split_kernel<<<512, 256>>>(W_ih, pIhHi, pIhLo, (size_t)4 * HID * HID);
    split_kernel<<<512, 256>>>(W_hh, pHhHi, pHhLo, (size_t)4 * HID * HID);
    closed1_kernel<<<C1, 64>>>(fused, c1_W, c1_b);
    closed2_kernel<<<32, 128>>>(c2_W, c2_b, out);

    dim3 ggrid(4 * HID / 64, KSG);   // (48, 4)
    for (int t = 0; t < TLEN; ++t) {
        gates_mma<<<ggrid, 256>>>(t, out);
        cell_kernel<<<(B * HID + 255) / 256, 256>>>(b_ih, b_hh, t);
        logits_mma<<<GRID_L, 256, 2 * LSTG>>>(out_b, t);
    }
    final_kernel<<<1, 64>>>(out);
}

// round 15
// speedup vs baseline: 1.5338x; 1.5338x over previous
#include <cuda_runtime.h>
#include <cuda_bf16.h>
#include <cstdint>

#define B    64
#define HID  768
#define VSZ  30000
#define TLEN 32
#define C1   512

// logits HMMA tiling (round-6/10 proven: MT=64, static smem, reg prefetch)
#define MT      64
#define KC      64
#define NCHUNK  (HID / KC)              // 12
#define GRID_L  ((VSZ + MT - 1) / MT)   // 469

// gates HMMA tiling (round-7/10 proven)
#define KSG     4                       // split-K
#define CHG     6                       // chunks of 64 per split (384 k)

__device__ float g_c[B * HID];          // transposed: [u][b]
__device__ float g_hidden[B * C1];
__device__ unsigned long long g_amax[2][B];
__device__ float g_gpartT[KSG][4 * HID][B];
__device__ __nv_bfloat16 g_Whi[(size_t)VSZ * HID];
__device__ __nv_bfloat16 g_Wlo[(size_t)VSZ * HID];
__device__ __nv_bfloat16 g_Ehi[(size_t)VSZ * HID];
__device__ __nv_bfloat16 g_Elo[(size_t)VSZ * HID];
__device__ __nv_bfloat16 g_WihHi[4 * HID * HID];
__device__ __nv_bfloat16 g_WihLo[4 * HID * HID];
__device__ __nv_bfloat16 g_WhhHi[4 * HID * HID];
__device__ __nv_bfloat16 g_WhhLo[4 * HID * HID];
__device__ __nv_bfloat16 g_hhi[B * HID];
__device__ __nv_bfloat16 g_hlo[B * HID];

__device__ __forceinline__ unsigned int ford(float f) {
    unsigned int u = __float_as_uint(f);
    return u ^ (((int)u >> 31) | 0x80000000u);
}
__device__ __forceinline__ float sigm(float x) { return 1.0f / (1.0f + expf(-x)); }

__device__ __forceinline__ uint32_t smem_u32(const void* p) {
    uint32_t a;
    asm("{ .reg .u64 t; cvta.to.shared.u64 t, %1; cvt.u32.u64 %0, t; }" : "=r"(a) : "l"(p));
    return a;
}

#define LDSM4(r0, r1, r2, r3, addr) \
    asm volatile("ldmatrix.sync.aligned.m8n8.x4.shared.b16 {%0,%1,%2,%3}, [%4];" \
                 : "=r"(r0), "=r"(r1), "=r"(r2), "=r"(r3) : "r"(addr))

#define MMA16816(d, a, bf) \
    asm volatile("mma.sync.aligned.m16n8k16.row.col.f32.bf16.bf16.f32 " \
                 "{%0,%1,%2,%3}, {%4,%5,%6,%7}, {%8,%9}, {%0,%1,%2,%3};" \
                 : "+f"((d)[0]), "+f"((d)[1]), "+f"((d)[2]), "+f"((d)[3]) \
                 : "r"((a)[0]), "r"((a)[1]), "r"((a)[2]), "r"((a)[3]), \
                   "r"((bf)[0]), "r"((bf)[1]))

// ---------------------------------------------------------------------------
__global__ void init_kernel(const float* __restrict__ fused) {
    int i = blockIdx.x * blockDim.x + threadIdx.x;
    if (i < B * HID) {
        float v = fused[i];
        __nv_bfloat16 hi = __float2bfloat16(v);
        g_hhi[i] = hi;
        g_hlo[i] = __float2bfloat16(v - __bfloat162float(hi));
        g_c[i] = 0.0f;
    }
    if (blockIdx.x == 0 && threadIdx.x < B) {
        g_amax[0][threadIdx.x] = 0ull;
        g_amax[1][threadIdx.x] = 0ull;
    }
}

// ---------------------------------------------------------------------------
// fp32 -> bf16 hi/lo split with PACKED 8B stores (was 8x scattered 2B stores)
// ---------------------------------------------------------------------------
__global__ void split_kernel(const float* __restrict__ src,
                             __nv_bfloat16* __restrict__ hi,
                             __nv_bfloat16* __restrict__ lo, size_t n) {
    size_t stride = (size_t)gridDim.x * blockDim.x * 4;
    for (size_t i = ((size_t)blockIdx.x * blockDim.x + threadIdx.x) * 4; i < n; i += stride) {
        float4 x = *(const float4*)(src + i);
        __nv_bfloat162 h01, h23, l01, l23;
        h01.x = __float2bfloat16(x.x); h01.y = __float2bfloat16(x.y);
        h23.x = __float2bfloat16(x.z); h23.y = __float2bfloat16(x.w);
        l01.x = __float2bfloat16(x.x - __bfloat162float(h01.x));
        l01.y = __float2bfloat16(x.y - __bfloat162float(h01.y));
        l23.x = __float2bfloat16(x.z - __bfloat162float(h23.x));
        l23.y = __float2bfloat16(x.w - __bfloat162float(h23.y));
        uint2 hv, lv;
        hv.x = *reinterpret_cast<uint32_t*>(&h01);
        hv.y = *reinterpret_cast<uint32_t*>(&h23);
        lv.x = *reinterpret_cast<uint32_t*>(&l01);
        lv.y = *reinterpret_cast<uint32_t*>(&l23);
        *(uint2*)(hi + i) = hv;
        *(uint2*)(lo + i) = lv;
    }
}

// ---------------------------------------------------------------------------
__global__ void closed1_kernel(const float* __restrict__ fused,
                               const float* __restrict__ c1_W,
                               const float* __restrict__ c1_b) {
    __shared__ float w[HID];
    int j = blockIdx.x;
    for (int k = threadIdx.x; k < HID; k += 64) w[k] = c1_W[j * HID + k];
    __syncthreads();
    int b = threadIdx.x;
    float acc = 0.0f;
    for (int k = 0; k < HID; ++k) acc += fused[b * HID + k] * w[k];
    acc += c1_b[j];
    g_hidden[b * C1 + j] = fmaxf(acc, 0.0f);
}

__global__ void closed2_kernel(const float* __restrict__ c2_W,
                               const float* __restrict__ c2_b,
                               float* __restrict__ out) {
    int wid = threadIdx.x >> 5, lane = threadIdx.x & 31;
    int o = blockIdx.x * 4 + wid;
    int b = o >> 1, cls = o & 1;
    float acc = 0.0f;
    for (int k = lane; k < C1; k += 32)
        acc += g_hidden[b * C1 + k] * c2_W[cls * C1 + k];
#pragma unroll
    for (int off = 16; off; off >>= 1)
        acc += __shfl_xor_sync(0xFFFFFFFFu, acc, off);
    if (lane == 0) out[b * 2 + cls] = acc + c2_b[cls];
}

// ---------------------------------------------------------------------------
// gates via HMMA split-bf16 (exact round-7/10 structure — proven)
// ---------------------------------------------------------------------------
__global__ void __launch_bounds__(256, 2)
gates_mma(int t, float* __restrict__ out) {
    __shared__ __align__(128) __nv_bfloat16 sAhi[64 * KC];
    __shared__ __align__(128) __nv_bfloat16 sAlo[64 * KC];
    __shared__ __align__(128) __nv_bfloat16 sBhi[B * KC];
    __shared__ __align__(128) __nv_bfloat16 sBlo[B * KC];
    __shared__ int tok_s[B];

    const int tid = threadIdx.x, wid = tid >> 5, lane = tid & 31;
    const int mw = wid >> 1, nw = wid & 1;
    const int mtile = blockIdx.x;
    const int ks = blockIdx.y;
    const bool is_x = ks < 2;
    const int kbase = (ks & 1) * 384;

    if (tid < B) {
        int tok = 0;
        if (t > 0) tok = (int)(~(unsigned int)(g_amax[(t - 1) & 1][tid]));
        tok_s[tid] = tok;
        if (mtile == 0 && ks == 0) {
            g_amax[t & 1][tid] = 0ull;
            if (t > 0) out[2 * B + tid * TLEN + (t - 1)] = (float)tok;
        }
    }
    __syncthreads();

    const __nv_bfloat16* srcp[8];
    uint32_t dsta[8];
#pragma unroll
    for (int i = 0; i < 8; ++i) {
        int s = tid + i * 256;
        int r = (s & 511) >> 3, g = s & 7;
        uint32_t dst = (uint32_t)(r * 128 + ((g ^ (r & 7)) * 16));
        if (s < 512) {
            int m = mtile * 64 + r;
            srcp[i] = (is_x ? g_WihHi : g_WhhHi) + (size_t)m * HID + kbase + g * 8;
            dsta[i] = smem_u32(sAhi) + dst;
        } else if (s < 1024) {
            int m = mtile * 64 + r;
            srcp[i] = (is_x ? g_WihLo : g_WhhLo) + (size_t)m * HID + kbase + g * 8;
            dsta[i] = smem_u32(sAlo) + dst;
        } else if (s < 1536) {
            srcp[i] = is_x ? (g_Ehi + (size_t)tok_s[r] * HID + kbase + g * 8)
                           : (g_hhi + r * HID + kbase + g * 8);
            dsta[i] = smem_u32(sBhi) + dst;
        } else {
            srcp[i] = is_x ? (g_Elo + (size_t)tok_s[r] * HID + kbase + g * 8)
                           : (g_hlo + r * HID + kbase + g * 8);
            dsta[i] = smem_u32(sBlo) + dst;
        }
    }

    const int mA = mw * 16 + ((lane >> 3) & 1) * 8 + (lane & 7);
    const int gAo = lane >> 4;
    const int nB = nw * 32 + ((lane >> 4) & 1) * 8 + (lane & 7);
    const int gBo = (lane >> 3) & 1;
    const uint32_t sAhiB = smem_u32(sAhi), sAloB = smem_u32(sAlo);
    const uint32_t sBhiB = smem_u32(sBhi), sBloB = smem_u32(sBlo);

    float acc[4][4];
#pragma unroll
    for (int n = 0; n < 4; ++n)
#pragma unroll
        for (int j = 0; j < 4; ++j) acc[n][j] = 0.0f;

    uint4 pf[8];
#pragma unroll
    for (int i = 0; i < 8; ++i) { pf[i] = *(const uint4*)srcp[i]; srcp[i] += KC; }

    for (int c = 0; c < CHG; ++c) {
#pragma unroll
        for (int i = 0; i < 8; ++i)
            asm volatile("st.shared.v4.b32 [%0], {%1, %2, %3, %4};"
                         :: "r"(dsta[i]), "r"(pf[i].x), "r"(pf[i].y),
                            "r"(pf[i].z), "r"(pf[i].w) : "memory");
        __syncthreads();

        if (c + 1 < CHG) {
#pragma unroll
            for (int i = 0; i < 8; ++i) { pf[i] = *(const uint4*)srcp[i]; srcp[i] += KC; }
        }

#pragma unroll
        for (int step = 0; step < 4; ++step) {
            const int g0 = step * 2;
            const int gA = g0 + gAo;
            const uint32_t offA = (uint32_t)(mA * 128 + ((gA ^ (mA & 7)) * 16));
            uint32_t ahi[4], alo[4];
            LDSM4(ahi[0], ahi[1], ahi[2], ahi[3], sAhiB + offA);
            LDSM4(alo[0], alo[1], alo[2], alo[3], sAloB + offA);

            uint32_t bhi[4][2], blo[4][2];
#pragma unroll
            for (int ntp = 0; ntp < 2; ++ntp) {
                const int nr = nB + ntp * 16;
                const int gB = g0 + gBo;
                const uint32_t offB = (uint32_t)(nr * 128 + ((gB ^ (nr & 7)) * 16));
                LDSM4(bhi[ntp * 2][0], bhi[ntp * 2][1],
                      bhi[ntp * 2 + 1][0], bhi[ntp * 2 + 1][1], sBhiB + offB);
                LDSM4(blo[ntp * 2][0], blo[ntp * 2][1],
                      blo[ntp * 2 + 1][0], blo[ntp * 2 + 1][1], sBloB + offB);
            }
#pragma unroll
            for (int n = 0; n < 4; ++n) {
                MMA16816(acc[n], ahi, bhi[n]);
                MMA16816(acc[n], ahi, blo[n]);
                MMA16816(acc[n], alo, bhi[n]);
            }
        }
        __syncthreads();
    }

    const int laneg = lane >> 2, lane4 = lane & 3;
    const int row_lo = mtile * 64 + mw * 16 + laneg;
    const int row_hi = row_lo + 8;
#pragma unroll
    for (int n = 0; n < 4; ++n) {
        int col = nw * 32 + n * 8 + lane4 * 2;
        *(float2*)&g_gpartT[ks][row_lo][col] = make_float2(acc[n][0], acc[n][1]);
        *(float2*)&g_gpartT[ks][row_hi][col] = make_float2(acc[n][2], acc[n][3]);
    }
}

// ---------------------------------------------------------------------------
// cell: reduce KSG partials (fixed order), biases, LSTM nonlinearities,
// emit bf16 hi/lo split of h. (exact round-7/10)
// ---------------------------------------------------------------------------
__global__ void cell_kernel(const float* __restrict__ b_ih,
                            const float* __restrict__ b_hh, int t) {
    int idx = blockIdx.x * blockDim.x + threadIdx.x;
    if (idx >= B * HID) return;
    int b = idx & (B - 1), u = idx >> 6;

    float gi = b_ih[u] + b_hh[u];
    float gf = b_ih[HID + u] + b_hh[HID + u];
    float gg = b_ih[2 * HID + u] + b_hh[2 * HID + u];
    float go = b_ih[3 * HID + u] + b_hh[3 * HID + u];
#pragma unroll
    for (int s = 0; s < KSG; ++s) {
        gi += g_gpartT[s][u][b];
        gf += g_gpartT[s][HID + u][b];
        gg += g_gpartT[s][2 * HID + u][b];
        go += g_gpartT[s][3 * HID + u][b];
    }
    float cn = sigm(gf) * g_c[u * B + b] + sigm(gi) * tanhf(gg);
    g_c[u * B + b] = cn;
    float hn = sigm(go) * tanhf(cn);
    __nv_bfloat16 hi = __float2bfloat16(hn);
    g_hhi[b * HID + u] = hi;
    g_hlo[b * HID + u] = __float2bfloat16(hn - __bfloat162float(hi));
}

// ---------------------------------------------------------------------------
// logits via HMMA split-bf16 — EXACT round-6/10 version (MT=64, static smem,
// register prefetch, grid 469). Proven.
// ---------------------------------------------------------------------------
__global__ void __launch_bounds__(256, 2)
logits_mma(const float* __restrict__ out_b, int t) {
    __shared__ __align__(128) __nv_bfloat16 sWhi[MT * KC];
    __shared__ __align__(128) __nv_bfloat16 sWlo[MT * KC];
    __shared__ __align__(128) __nv_bfloat16 sHhi[B * KC];
    __shared__ __align__(128) __nv_bfloat16 sHlo[B * KC];
    __shared__ unsigned long long skeys[4][B];

    const int tid = threadIdx.x, wid = tid >> 5, lane = tid & 31;
    const int mw = wid >> 1, nw = wid & 1;
    const int v0 = blockIdx.x * MT;

    const __nv_bfloat16* srcp[8];
    uint32_t dsta[8];
#pragma unroll
    for (int i = 0; i < 8; ++i) {
        int s = tid + i * 256;
        int r = (s & 511) >> 3, g = s & 7;
        uint32_t dst = (uint32_t)(r * 128 + ((g ^ (r & 7)) * 16));
        if (s < 512) {
            int v = v0 + r; if (v >= VSZ) v = VSZ - 1;
            srcp[i] = g_Whi + (size_t)v * HID + g * 8;
            dsta[i] = smem_u32(sWhi) + dst;
        } else if (s < 1024) {
            int v = v0 + r; if (v >= VSZ) v = VSZ - 1;
            srcp[i] = g_Wlo + (size_t)v * HID + g * 8;
            dsta[i] = smem_u32(sWlo) + dst;
        } else if (s < 1536) {
            srcp[i] = g_hhi + r * HID + g * 8;
            dsta[i] = smem_u32(sHhi) + dst;
        } else {
            srcp[i] = g_hlo + r * HID + g * 8;
            dsta[i] = smem_u32(sHlo) + dst;
        }
    }

    const int mA = mw * 16 + ((lane >> 3) & 1) * 8 + (lane & 7);
    const int gAo = lane >> 4;
    const int nB = nw * 32 + ((lane >> 4) & 1) * 8 + (lane & 7);
    const int gBo = (lane >> 3) & 1;
    const uint32_t sWhiB = smem_u32(sWhi), sWloB = smem_u32(sWlo);
    const uint32_t sHhiB = smem_u32(sHhi), sHloB = smem_u32(sHlo);

    float acc[4][4];
#pragma unroll
    for (int n = 0; n < 4; ++n)
#pragma unroll
        for (int j = 0; j < 4; ++j) acc[n][j] = 0.0f;

    uint4 pf[8];
#pragma unroll
    for (int i = 0; i < 8; ++i) { pf[i] = *(const uint4*)srcp[i]; srcp[i] += KC; }

    for (int c = 0; c < NCHUNK; ++c) {
#pragma unroll
        for (int i = 0; i < 8; ++i)
            asm volatile("st.shared.v4.b32 [%0], {%1, %2, %3, %4};"
                         :: "r"(dsta[i]), "r"(pf[i].x), "r"(pf[i].y),
                            "r"(pf[i].z), "r"(pf[i].w) : "memory");
        __syncthreads();

        if (c + 1 < NCHUNK) {
#pragma unroll
            for (int i = 0; i < 8; ++i) { pf[i] = *(const uint4*)srcp[i]; srcp[i] += KC; }
        }

#pragma unroll
        for (int step = 0; step < 4; ++step) {
            const int g0 = step * 2;
            const int gA = g0 + gAo;
            const uint32_t offA = (uint32_t)(mA * 128 + ((gA ^ (mA & 7)) * 16));
            uint32_t ahi[4], alo[4];
            LDSM4(ahi[0], ahi[1], ahi[2], ahi[3], sWhiB + offA);
            LDSM4(alo[0], alo[1], alo[2], alo[3], sWloB + offA);

            uint32_t bhi[4][2], blo[4][2];
#pragma unroll
            for (int ntp = 0; ntp < 2; ++ntp) {
                const int nr = nB + ntp * 16;
                const int gB = g0 + gBo;
                const uint32_t offB = (uint32_t)(nr * 128 + ((gB ^ (nr & 7)) * 16));
                LDSM4(bhi[ntp * 2][0], bhi[ntp * 2][1],
                      bhi[ntp * 2 + 1][0], bhi[ntp * 2 + 1][1], sHhiB + offB);
                LDSM4(blo[ntp * 2][0], blo[ntp * 2][1],
                      blo[ntp * 2 + 1][0], blo[ntp * 2 + 1][1], sHloB + offB);
            }
#pragma unroll
            for (int n = 0; n < 4; ++n) {
                MMA16816(acc[n], ahi, bhi[n]);
                MMA16816(acc[n], ahi, blo[n]);
                MMA16816(acc[n], alo, bhi[n]);
            }
        }
        __syncthreads();
    }

    const int laneg = lane >> 2, lane4 = lane & 3;
    const int m_lo = v0 + mw * 16 + laneg;
    const int m_hi = m_lo + 8;
    const bool val_lo = m_lo < VSZ, val_hi = m_hi < VSZ;
    const float bias_lo = val_lo ? out_b[m_lo] : 0.0f;
    const float bias_hi = val_hi ? out_b[m_hi] : 0.0f;
    const unsigned int ni_lo = ~(unsigned int)m_lo, ni_hi = ~(unsigned int)m_hi;

#pragma unroll
    for (int n = 0; n < 4; ++n) {
        unsigned long long kA = 0ull, kB = 0ull;
        if (val_lo) {
            kA = ((unsigned long long)ford(acc[n][0] + bias_lo) << 32) | ni_lo;
            kB = ((unsigned long long)ford(acc[n][1] + bias_lo) << 32) | ni_lo;
        }
        if (val_hi) {
            unsigned long long k2 = ((unsigned long long)ford(acc[n][2] + bias_hi) << 32) | ni_hi;
            unsigned long long k3 = ((unsigned long long)ford(acc[n][3] + bias_hi) << 32) | ni_hi;
            if (k2 > kA) kA = k2;
            if (k3 > kB) kB = k3;
        }
#pragma unroll
        for (int off = 4; off < 32; off <<= 1) {
            unsigned long long oA = __shfl_xor_sync(0xFFFFFFFFu, kA, off);
            unsigned long long oB = __shfl_xor_sync(0xFFFFFFFFu, kB, off);
            if (oA > kA) kA = oA;
            if (oB > kB) kB = oB;
        }
        if (laneg == 0) {
            int ncol = nw * 32 + n * 8 + lane4 * 2;
            skeys[mw][ncol]     = kA;
            skeys[mw][ncol + 1] = kB;
        }
    }
    __syncthreads();
    if (tid < B) {
        unsigned long long k = skeys[0][tid];
        if (skeys[1][tid] > k) k = skeys[1][tid];
        if (skeys[2][tid] > k) k = skeys[2][tid];
        if (skeys[3][tid] > k) k = skeys[3][tid];
        atomicMax(&g_amax[t & 1][tid], k);
    }
}

// ---------------------------------------------------------------------------
__global__ void final_kernel(float* __restrict__ out) {
    int b = threadIdx.x;
    if (b < B) {
        int tok = (int)(~(unsigned int)(g_amax[(TLEN - 1) & 1][b]));
        out[2 * B + b * TLEN + (TLEN - 1)] = (float)tok;
    }
}

// ---------------------------------------------------------------------------
extern "C" void kernel_launch(void* const* d_in, const int* in_sizes, int n_in,
                              void* d_out, int out_size) {
    const float* fused = (const float*)d_in[0];
    const float* emb   = (const float*)d_in[1];
    const float* W_ih  = (const float*)d_in[2];
    const float* W_hh  = (const float*)d_in[3];
    const float* b_ih  = (const float*)d_in[4];
    const float* b_hh  = (const float*)d_in[5];
    const float* out_W = (const float*)d_in[6];
    const float* out_b = (const float*)d_in[7];
    const float* c1_W  = (const float*)d_in[8];
    const float* c1_b  = (const float*)d_in[9];
    const float* c2_W  = (const float*)d_in[10];
    const float* c2_b  = (const float*)d_in[11];
    float* out = (float*)d_out;

    __nv_bfloat16 *pWhi, *pWlo, *pEhi, *pElo, *pIhHi, *pIhLo, *pHhHi, *pHhLo;
    cudaGetSymbolAddress((void**)&pWhi, g_Whi);
    cudaGetSymbolAddress((void**)&pWlo, g_Wlo);
    cudaGetSymbolAddress((void**)&pEhi, g_Ehi);
    cudaGetSymbolAddress((void**)&pElo, g_Elo);
    cudaGetSymbolAddress((void**)&pIhHi, g_WihHi);
    cudaGetSymbolAddress((void**)&pIhLo, g_WihLo);
    cudaGetSymbolAddress((void**)&pHhHi, g_WhhHi);
    cudaGetSymbolAddress((void**)&pHhLo, g_WhhLo);

    init_kernel<<<(B * HID + 255) / 256, 256>>>(fused);
    split_kernel<<<2048, 256>>>(out_W, pWhi, pWlo, (size_t)VSZ * HID);
    split_kernel<<<2048, 256>>>(emb, pEhi, pElo, (size_t)VSZ * HID);
    split_kernel<<<512, 256>>>(W_ih, pIhHi, pIhLo, (size_t)4 * HID * HID);
    split_kernel<<<512, 256>>>(W_hh, pHhHi, pHhLo, (size_t)4 * HID * HID);
    closed1_kernel<<<C1, 64>>>(fused, c1_W, c1_b);
    closed2_kernel<<<32, 128>>>(c2_W, c2_b, out);

    dim3 ggrid(4 * HID / 64, KSG);   // (48, 4)
    for (int t = 0; t < TLEN; ++t) {
        gates_mma<<<ggrid, 256>>>(t, out);
        cell_kernel<<<(B * HID + 255) / 256, 256>>>(b_ih, b_hh, t);
        logits_mma<<<GRID_L, 256>>>(out_b, t);
    }
    final_kernel<<<1, 64>>>(out);
}